// round 2
// baseline (speedup 1.0000x reference)
#include <cuda_runtime.h>
#include <cstdint>

#define IDIM    256
#define HDIM    512
#define ODIM    10
#define BATCH   64
#define TSTEPS  2048
#define KC      768            // H + I
#define GBLOCKS 64
#define NB      32             // gate rows per block
#define NH      8              // h indices per block (NB = 4*NH)
#define NTHREADS 256
#define KT      256            // k-chunk staged per pass (3 chunks: h lo, h hi, x_t)
#define RS      260            // padded row stride (== 4 mod 32 -> conflict-free frag loads)
#define NK8     (KC/8)         // 96
#define K8PC    (KT/8)         // 32

// persistent device state (static allocation is the sanctioned scratch path)
__device__ float        g_h[2][BATCH][HDIM];   // double-buffered hidden state
__device__ unsigned int g_bar[TSTEPS];         // one barrier counter per step

__device__ __forceinline__ float to_tf32(float x) {
    float r;
    asm("cvt.rna.tf32.f32 %0, %1;" : "=f"(r) : "f"(x));
    return r;
}

__device__ __forceinline__ void mma_tf32(float c[4],
                                         uint32_t a0, uint32_t a1, uint32_t a2, uint32_t a3,
                                         uint32_t b0, uint32_t b1) {
    asm volatile(
        "mma.sync.aligned.m16n8k8.row.col.f32.tf32.tf32.f32 "
        "{%0,%1,%2,%3}, {%4,%5,%6,%7}, {%8,%9}, {%0,%1,%2,%3};"
        : "+f"(c[0]), "+f"(c[1]), "+f"(c[2]), "+f"(c[3])
        : "r"(a0), "r"(a1), "r"(a2), "r"(a3), "r"(b0), "r"(b1));
}

__global__ void init_kernel() {
    int idx = blockIdx.x * blockDim.x + threadIdx.x;
    int stride = gridDim.x * blockDim.x;
    float* h = &g_h[0][0][0];
    for (int i = idx; i < 2 * BATCH * HDIM; i += stride) h[i] = 0.f;
    for (int i = idx; i < TSTEPS; i += stride) g_bar[i] = 0u;
}

__global__ void __launch_bounds__(NTHREADS, 1)
lstm_kernel(const float* __restrict__ x,
            const float* __restrict__ W_ih,
            const float* __restrict__ W_hh,
            const float* __restrict__ b_ih,
            const float* __restrict__ b_hh)
{
    extern __shared__ float sm[];
    // SMEM layout (floats):
    //   WB   : [NK8][2][32] float4 B-fragments of W_cat (tf32)      24576
    //   HS   : [64][RS] staged A tile (tf32)                        16640
    //   GS   : [64][NB] gate pre-activations (fp32)                  2048
    //   CS   : [64][NH] cell state (fp32, persistent)                 512
    //   BIAS : [NB]                                                    32
    float4* WB   = (float4*)sm;
    float*  HS   = sm + NK8 * 2 * 32 * 4;
    float*  GS   = HS + BATCH * RS;
    float*  CS   = GS + BATCH * NB;
    float*  BIAS = CS + BATCH * NH;

    const int tid  = threadIdx.x;
    const int bid  = blockIdx.x;
    const int warp = tid >> 5;
    const int lane = tid & 31;
    const int gid  = lane >> 2;   // groupID
    const int tig  = lane & 3;    // threadID in group
    const int mw   = warp >> 1;   // m16 tile (batch rows 16*mw..)
    const int nh   = warp & 1;    // n16 half

    // zero persistent cell state
    for (int i = tid; i < BATCH * NH; i += NTHREADS) CS[i] = 0.f;

    // biases: n_local = jj*4 + g ; global gate row = g*H + bid*NH + jj
    for (int i = tid; i < NB; i += NTHREADS) {
        int jj = i >> 2, g = i & 3;
        int grow = g * HDIM + bid * NH + jj;
        BIAS[i] = b_ih[grow] + b_hh[grow];
    }

    // stage W_cat as mma B fragments (done once, reused for all 2048 steps)
    for (int idx = tid; idx < NK8 * 2 * 32; idx += NTHREADS) {
        int K8  = idx >> 6;
        int rem = idx & 63;
        int nhs = rem >> 5;
        int ln  = rem & 31;
        int g2  = ln >> 2;
        int t2  = ln & 3;
        int k0  = K8 * 8 + t2;
        int nl0 = nhs * 16 + g2;
        int nl1 = nl0 + 8;
        int grow0 = (nl0 & 3) * HDIM + bid * NH + (nl0 >> 2);
        int grow1 = (nl1 & 3) * HDIM + bid * NH + (nl1 >> 2);
        float4 v;
        if (k0 < HDIM) {
            v.x = W_hh[grow0 * HDIM + k0];
            v.y = W_hh[grow0 * HDIM + k0 + 4];
            v.z = W_hh[grow1 * HDIM + k0];
            v.w = W_hh[grow1 * HDIM + k0 + 4];
        } else {
            v.x = W_ih[grow0 * IDIM + (k0 - HDIM)];
            v.y = W_ih[grow0 * IDIM + (k0 + 4 - HDIM)];
            v.z = W_ih[grow1 * IDIM + (k0 - HDIM)];
            v.w = W_ih[grow1 * IDIM + (k0 + 4 - HDIM)];
        }
        v.x = to_tf32(v.x); v.y = to_tf32(v.y);
        v.z = to_tf32(v.z); v.w = to_tf32(v.w);
        WB[idx] = v;
    }
    __syncthreads();

    const int m0 = mw * 16;

    for (int t = 0; t < TSTEPS; ++t) {
        float acc0[4] = {0.f, 0.f, 0.f, 0.f};
        float acc1[4] = {0.f, 0.f, 0.f, 0.f};
        const float* __restrict__ hprev = &g_h[t & 1][0][0];

        for (int ch = 0; ch < 3; ++ch) {
            __syncthreads();   // protect HS from previous chunk's readers
            // stage 64 x 256 tile of h_cat (tf32) into HS
            if (ch < 2) {
                for (int idx = tid; idx < BATCH * KT / 4; idx += NTHREADS) {
                    int row = idx >> 6;
                    int c4  = (idx & 63) << 2;
                    float4 v = *(const float4*)&hprev[row * HDIM + ch * KT + c4];
                    v.x = to_tf32(v.x); v.y = to_tf32(v.y);
                    v.z = to_tf32(v.z); v.w = to_tf32(v.w);
                    *(float4*)&HS[row * RS + c4] = v;
                }
            } else {
                for (int idx = tid; idx < BATCH * KT / 4; idx += NTHREADS) {
                    int row = idx >> 6;
                    int c4  = (idx & 63) << 2;
                    float4 v = *(const float4*)&x[((size_t)row * TSTEPS + t) * IDIM + c4];
                    v.x = to_tf32(v.x); v.y = to_tf32(v.y);
                    v.z = to_tf32(v.z); v.w = to_tf32(v.w);
                    *(float4*)&HS[row * RS + c4] = v;
                }
            }
            __syncthreads();

            const float4* __restrict__ wb = WB + ((ch * K8PC) * 2 + nh) * 32 + lane;
            #pragma unroll 8
            for (int k8 = 0; k8 < K8PC; ++k8) {
                const int cb = k8 * 8;
                const float* hp = &HS[(m0 + gid) * RS + cb + tig];
                uint32_t a0 = __float_as_uint(hp[0]);
                uint32_t a2 = __float_as_uint(hp[4]);
                uint32_t a1 = __float_as_uint(hp[8 * RS]);
                uint32_t a3 = __float_as_uint(hp[8 * RS + 4]);
                float4 b4 = wb[k8 * 64];
                mma_tf32(acc0, a0, a1, a2, a3,
                         __float_as_uint(b4.x), __float_as_uint(b4.y));
                mma_tf32(acc1, a0, a1, a2, a3,
                         __float_as_uint(b4.z), __float_as_uint(b4.w));
            }
        }

        // epilogue: scatter C fragments to GS
        __syncthreads();
        {
            int rbase = (m0 + gid) * NB + nh * 16 + 2 * tig;
            GS[rbase + 0]          = acc0[0];
            GS[rbase + 1]          = acc0[1];
            GS[rbase + 8 * NB + 0] = acc0[2];
            GS[rbase + 8 * NB + 1] = acc0[3];
            GS[rbase + 8 + 0]          = acc1[0];
            GS[rbase + 8 + 1]          = acc1[1];
            GS[rbase + 8 + 8 * NB + 0] = acc1[2];
            GS[rbase + 8 + 8 * NB + 1] = acc1[3];
        }
        __syncthreads();

        // pointwise LSTM cell (c stays in SMEM; h slice goes to the other buffer)
        float* __restrict__ hnext = &g_h[(t + 1) & 1][0][0];
        for (int p = tid; p < BATCH * NH; p += NTHREADS) {
            int b  = p >> 3;
            int jj = p & 7;
            float gi = GS[b * NB + jj * 4 + 0] + BIAS[jj * 4 + 0];
            float gf = GS[b * NB + jj * 4 + 1] + BIAS[jj * 4 + 1];
            float gg = GS[b * NB + jj * 4 + 2] + BIAS[jj * 4 + 2];
            float go = GS[b * NB + jj * 4 + 3] + BIAS[jj * 4 + 3];
            gi = 1.f / (1.f + __expf(-gi));
            gf = 1.f / (1.f + __expf(-gf));
            go = 1.f / (1.f + __expf(-go));
            gg = tanhf(gg);
            float c = gf * CS[p] + gi * gg;
            CS[p] = c;
            hnext[b * HDIM + bid * NH + jj] = go * tanhf(c);
        }

        // grid-wide barrier (release/acquire via threadfence; per-step counter slot)
        __threadfence();
        __syncthreads();
        if (tid == 0) {
            atomicAdd(&g_bar[t], 1u);
            while (*(volatile unsigned int*)&g_bar[t] < (unsigned)GBLOCKS) { }
        }
        __syncthreads();
        __threadfence();
    }
}

__global__ void fc_kernel(const float* __restrict__ W_fc,
                          const float* __restrict__ b_fc,
                          float* __restrict__ out)
{
    int b    = blockIdx.x;
    int warp = threadIdx.x >> 5;
    int lane = threadIdx.x & 31;
    if (warp >= ODIM) return;
    const float* h = &g_h[0][b][0];   // final h lives in buffer 0 (T even)
    float acc = 0.f;
    for (int k = lane; k < HDIM; k += 32)
        acc += h[k] * W_fc[warp * HDIM + k];
    #pragma unroll
    for (int off = 16; off; off >>= 1)
        acc += __shfl_xor_sync(0xffffffffu, acc, off);
    if (lane == 0) out[b * ODIM + warp] = acc + b_fc[warp];
}

extern "C" void kernel_launch(void* const* d_in, const int* in_sizes, int n_in,
                              void* d_out, int out_size)
{
    const float* x    = (const float*)d_in[0];
    const float* W_ih = (const float*)d_in[1];
    const float* W_hh = (const float*)d_in[2];
    const float* b_ih = (const float*)d_in[3];
    const float* b_hh = (const float*)d_in[4];
    const float* W_fc = (const float*)d_in[5];
    const float* b_fc = (const float*)d_in[6];
    float* out = (float*)d_out;

    const size_t SMEM = (size_t)(NK8 * 2 * 32 * 4      // WB
                                 + BATCH * RS          // HS
                                 + BATCH * NB          // GS
                                 + BATCH * NH          // CS
                                 + NB) * sizeof(float);

    cudaFuncSetAttribute(lstm_kernel,
                         cudaFuncAttributeMaxDynamicSharedMemorySize, (int)SMEM);

    init_kernel<<<64, 256>>>();
    lstm_kernel<<<GBLOCKS, NTHREADS, SMEM>>>(x, W_ih, W_hh, b_ih, b_hh);
    fc_kernel<<<BATCH, 320>>>(W_fc, b_fc, out);
}

// round 3
// speedup vs baseline: 1.1580x; 1.1580x over previous
#include <cuda_runtime.h>
#include <cstdint>

#define IDIM    256
#define HDIM    512
#define ODIM    10
#define BATCH   64
#define TSTEPS  2048
#define GB      64          // grid blocks (all co-resident)
#define NTH     256         // 8 warps
#define NH      8           // h columns owned per block

// persistent device state
__device__ float        g_h[2][BATCH][HDIM];   // double-buffered hidden state
__device__ unsigned int g_bar[TSTEPS];         // per-step arrival counters

__device__ __forceinline__ uint32_t tf32b(float x) {
    float r;
    asm("cvt.rna.tf32.f32 %0, %1;" : "=f"(r) : "f"(x));
    return __float_as_uint(r);
}

__device__ __forceinline__ void mma_tf32(float c[4],
                                         uint32_t a0, uint32_t a1, uint32_t a2, uint32_t a3,
                                         uint32_t b0, uint32_t b1) {
    asm("mma.sync.aligned.m16n8k8.row.col.f32.tf32.tf32.f32 "
        "{%0,%1,%2,%3}, {%4,%5,%6,%7}, {%8,%9}, {%0,%1,%2,%3};"
        : "+f"(c[0]), "+f"(c[1]), "+f"(c[2]), "+f"(c[3])
        : "r"(a0), "r"(a1), "r"(a2), "r"(a3), "r"(b0), "r"(b1));
}

__device__ __forceinline__ float sigf(float x)  { return 1.f / (1.f + __expf(-x)); }
__device__ __forceinline__ float tanhff(float x){ return 1.f - 2.f / (__expf(2.f * x) + 1.f); }

__global__ void init_kernel() {
    int idx = blockIdx.x * blockDim.x + threadIdx.x;
    int stride = gridDim.x * blockDim.x;
    float* h = &g_h[0][0][0];
    for (int i = idx; i < 2 * BATCH * HDIM; i += stride) h[i] = 0.f;
    for (int i = idx; i < TSTEPS; i += stride) g_bar[i] = 0u;
}

// 16 LDG.32 (cvt to tf32) for one k8 column-slice: 4 m16 tiles of the 64-row A panel
__device__ __forceinline__ void loadA(uint32_t a[16], const float* __restrict__ p0,
                                      int joff, int rstride /* elements per row */) {
    #pragma unroll
    for (int mt = 0; mt < 4; ++mt) {
        const float* p = p0 + (size_t)mt * 16 * rstride + joff;
        a[mt * 4 + 0] = tf32b(__ldcg(p));
        a[mt * 4 + 1] = tf32b(__ldcg(p + 8 * rstride));
        a[mt * 4 + 2] = tf32b(__ldcg(p + 4));
        a[mt * 4 + 3] = tf32b(__ldcg(p + 8 * rstride + 4));
    }
}

__device__ __forceinline__ void mma16(float acc[4][4][4], const uint32_t a[16],
                                      const uint32_t Bj[4][2]) {
    #pragma unroll
    for (int mt = 0; mt < 4; ++mt)
        #pragma unroll
        for (int nt = 0; nt < 4; ++nt)
            mma_tf32(acc[mt][nt], a[mt*4+0], a[mt*4+1], a[mt*4+2], a[mt*4+3],
                     Bj[nt][0], Bj[nt][1]);
}

__global__ void __launch_bounds__(NTH, 1)
lstm_kernel(const float* __restrict__ x,
            const float* __restrict__ W_ih,
            const float* __restrict__ W_hh,
            const float* __restrict__ b_ih,
            const float* __restrict__ b_hh)
{
    extern __shared__ float4 RB[];   // [8 warps][16 slots][32 lanes] partial C frags (64KB)

    const int tid  = threadIdx.x;
    const int bid  = blockIdx.x;
    const int w    = tid >> 5;
    const int lane = tid & 31;
    const int gid  = lane >> 2;
    const int tig  = lane & 3;

    // ---- one-time: gather B fragments (tf32) into registers --------------
    // warp w owns k8 slices: h: K8 = w*8 + j (j=0..7); x: K8 = 64 + w*4 + (j-8)
    uint32_t Bv[12][4][2];
    #pragma unroll
    for (int j = 0; j < 12; ++j) {
        const int K8 = (j < 8) ? (w * 8 + j) : (64 + w * 4 + (j - 8));
        const int kk = K8 * 8 + tig;
        #pragma unroll
        for (int nt = 0; nt < 4; ++nt) {
            int nl   = nt * 8 + gid;
            int grow = (nl & 3) * HDIM + bid * NH + (nl >> 2);
            float v0, v1;
            if (K8 < 64) { v0 = W_hh[grow * HDIM + kk];          v1 = W_hh[grow * HDIM + kk + 4]; }
            else         { v0 = W_ih[grow * IDIM + (kk - 512)];  v1 = W_ih[grow * IDIM + (kk - 508)]; }
            Bv[j][nt][0] = tf32b(v0);
            Bv[j][nt][1] = tf32b(v1);
        }
    }

    // ---- cell ownership: this thread finalizes 2 LSTM cells ---------------
    const int jj  = (w & 3) * 2 + (tig >> 1);   // h index within block's 8
    const int col = bid * NH + jj;              // global h column
    const float bI = b_ih[0*HDIM + col] + b_hh[0*HDIM + col];
    const float bF = b_ih[1*HDIM + col] + b_hh[1*HDIM + col];
    const float bG = b_ih[2*HDIM + col] + b_hh[2*HDIM + col];
    const float bO = b_ih[3*HDIM + col] + b_hh[3*HDIM + col];
    float creg[2] = {0.f, 0.f};

    // invariant x base pointer (row gid, col w*32+tig)
    const float* xp0 = x + (size_t)gid * TSTEPS * IDIM + w * 32 + tig;

    for (int t = 0; t < TSTEPS; ++t) {
        float acc[4][4][4];
        #pragma unroll
        for (int mt = 0; mt < 4; ++mt)
            #pragma unroll
            for (int nt = 0; nt < 4; ++nt)
                #pragma unroll
                for (int e = 0; e < 4; ++e) acc[mt][nt][e] = 0.f;

        // ---------- x phase (independent of barrier) ----------
        {
            const float* xb = xp0 + (size_t)t * IDIM;
            uint32_t A0[16], A1[16];
            loadA(A0, xb, 0, TSTEPS * IDIM);
            #pragma unroll
            for (int j = 0; j < 4; ++j) {
                if (j < 3) loadA((j & 1) ? A0 : A1, xb, (j + 1) * 8, TSTEPS * IDIM);
                mma16(acc, (j & 1) ? A1 : A0, Bv[8 + j]);
            }
        }

        // ---------- wait for h_t ----------
        if (t > 0) {
            if (tid == 0) {
                volatile unsigned int* p = &g_bar[t - 1];
                while (*p < (unsigned)GB) { }
            }
            __syncthreads();
        }

        // ---------- h phase ----------
        {
            const float* hb = &g_h[t & 1][0][0] + gid * HDIM + w * 64 + tig;
            uint32_t A0[16], A1[16];
            loadA(A0, hb, 0, HDIM);
            #pragma unroll
            for (int j = 0; j < 8; ++j) {
                if (j < 7) loadA((j & 1) ? A0 : A1, hb, (j + 1) * 8, HDIM);
                mma16(acc, (j & 1) ? A1 : A0, Bv[j]);
            }
        }

        // ---------- cross-warp k-reduction in fragment space ----------
        #pragma unroll
        for (int mt = 0; mt < 4; ++mt)
            #pragma unroll
            for (int nt = 0; nt < 4; ++nt)
                RB[(w * 16 + mt * 4 + nt) * 32 + lane] =
                    make_float4(acc[mt][nt][0], acc[mt][nt][1], acc[mt][nt][2], acc[mt][nt][3]);
        __syncthreads();

        float* __restrict__ hnext = &g_h[(t + 1) & 1][0][0];
        const bool odd = (tig & 1);

        #pragma unroll
        for (int pos = 0; pos < 2; ++pos) {
            const int s = w + pos * 8;
            float4 F = RB[(0 * 16 + s) * 32 + lane];
            #pragma unroll
            for (int ws = 1; ws < 8; ++ws) {
                float4 T = RB[(ws * 16 + s) * 32 + lane];
                F.x += T.x; F.y += T.y; F.z += T.z; F.w += T.w;
            }
            // exchange gate pairs: even lane ends with cell b_lo, odd with b_hi
            float sx = odd ? F.x : F.z;
            float sy = odd ? F.y : F.w;
            float rx = __shfl_xor_sync(0xffffffffu, sx, 1);
            float ry = __shfl_xor_sync(0xffffffffu, sy, 1);
            float gi = odd ? rx : F.x;
            float gf = odd ? ry : F.y;
            float gg = odd ? F.z : rx;
            float go = odd ? F.w : ry;

            gi = sigf(gi + bI);
            gf = sigf(gf + bF);
            go = sigf(go + bO);
            gg = tanhff(gg + bG);
            float c = gf * creg[pos] + gi * gg;
            creg[pos] = c;
            float hv = go * tanhff(c);

            const int mt = s >> 2;
            const int b  = mt * 16 + gid + (odd ? 8 : 0);
            __stcg(&hnext[b * HDIM + col], hv);
        }

        // ---------- release h_{t+1} ----------
        __threadfence();
        __syncthreads();
        if (tid == 0) atomicAdd(&g_bar[t], 1u);
    }
}

__global__ void fc_kernel(const float* __restrict__ W_fc,
                          const float* __restrict__ b_fc,
                          float* __restrict__ out)
{
    int b    = blockIdx.x;
    int warp = threadIdx.x >> 5;
    int lane = threadIdx.x & 31;
    if (warp >= ODIM) return;
    const float* h = &g_h[0][b][0];   // T even -> final h in buffer 0
    float acc = 0.f;
    for (int k = lane; k < HDIM; k += 32)
        acc += h[k] * W_fc[warp * HDIM + k];
    #pragma unroll
    for (int off = 16; off; off >>= 1)
        acc += __shfl_xor_sync(0xffffffffu, acc, off);
    if (lane == 0) out[b * ODIM + warp] = acc + b_fc[warp];
}

extern "C" void kernel_launch(void* const* d_in, const int* in_sizes, int n_in,
                              void* d_out, int out_size)
{
    const float* x    = (const float*)d_in[0];
    const float* W_ih = (const float*)d_in[1];
    const float* W_hh = (const float*)d_in[2];
    const float* b_ih = (const float*)d_in[3];
    const float* b_hh = (const float*)d_in[4];
    const float* W_fc = (const float*)d_in[5];
    const float* b_fc = (const float*)d_in[6];
    float* out = (float*)d_out;

    const int SMEM = 8 * 16 * 32 * (int)sizeof(float4);   // 64 KB
    cudaFuncSetAttribute(lstm_kernel,
                         cudaFuncAttributeMaxDynamicSharedMemorySize, SMEM);

    init_kernel<<<64, 256>>>();
    lstm_kernel<<<GB, NTH, SMEM>>>(x, W_ih, W_hh, b_ih, b_hh);
    fc_kernel<<<BATCH, 320>>>(W_fc, b_fc, out);
}

// round 7
// speedup vs baseline: 1.7410x; 1.5035x over previous
#include <cuda_runtime.h>
#include <cuda_fp16.h>
#include <cstdint>

#define IDIM    256
#define HDIM    512
#define ODIM    10
#define BATCH   64
#define TSTEPS  2048
#define GB      64          // grid blocks (all co-resident)
#define NTH     256         // 8 warps
#define NH      8           // h columns owned per block

// persistent device state (static __device__ is the sanctioned scratch path)
__device__ __half       g_h[2][BATCH][HDIM];          // double-buffered hidden state (fp16)
__device__ __half       g_x[BATCH][TSTEPS][IDIM];     // fp16 copy of x (converted once)
__device__ unsigned int g_bar[TSTEPS];                // per-step arrival counters

__device__ __forceinline__ uint32_t h2u(__half2 v) {
    uint32_t r;
    __builtin_memcpy(&r, &v, sizeof(r));
    return r;
}

__device__ __forceinline__ void mma_f16(float c[4],
                                        uint32_t a0, uint32_t a1, uint32_t a2, uint32_t a3,
                                        uint32_t b0, uint32_t b1) {
    asm("mma.sync.aligned.m16n8k16.row.col.f32.f16.f16.f32 "
        "{%0,%1,%2,%3}, {%4,%5,%6,%7}, {%8,%9}, {%0,%1,%2,%3};"
        : "+f"(c[0]), "+f"(c[1]), "+f"(c[2]), "+f"(c[3])
        : "r"(a0), "r"(a1), "r"(a2), "r"(a3), "r"(b0), "r"(b1));
}

__device__ __forceinline__ float sigf(float x)  { return 1.f / (1.f + __expf(-x)); }
__device__ __forceinline__ float tanhff(float x){ return 1.f - 2.f / (__expf(2.f * x) + 1.f); }

__global__ void init_kernel() {
    int idx = blockIdx.x * blockDim.x + threadIdx.x;
    int stride = gridDim.x * blockDim.x;
    __half* h = &g_h[0][0][0];
    for (int i = idx; i < 2 * BATCH * HDIM; i += stride) h[i] = __float2half(0.f);
    for (int i = idx; i < TSTEPS; i += stride) g_bar[i] = 0u;
}

// one-time fp32 -> fp16 conversion of x (8 floats / thread-iter)
__global__ void convert_x_kernel(const float* __restrict__ x) {
    const int N8 = BATCH * TSTEPS * IDIM / 8;
    uint2* dst = (uint2*)&g_x[0][0][0];
    int idx = blockIdx.x * blockDim.x + threadIdx.x;
    int stride = gridDim.x * blockDim.x;
    for (int i = idx; i < N8; i += stride) {
        float4 v0 = __ldcg((const float4*)x + 2 * i);
        float4 v1 = __ldcg((const float4*)x + 2 * i + 1);
        uint2 o;
        o.x = h2u(__floats2half2_rn(v0.x, v0.y));
        o.y = h2u(__floats2half2_rn(v0.z, v0.w));
        dst[2 * i] = o;
        o.x = h2u(__floats2half2_rn(v1.x, v1.y));
        o.y = h2u(__floats2half2_rn(v1.z, v1.w));
        dst[2 * i + 1] = o;
    }
}

// 16 half2 LDGs: A fragments for one k16 chunk over the 4 m16 tiles (64 rows).
// p0 points at (row 0, this chunk's col base + 2*tig), rs = row stride in halves.
__device__ __forceinline__ void loadA(uint32_t a[16], const __half* __restrict__ p0,
                                      int rs) {
    #pragma unroll
    for (int mt = 0; mt < 4; ++mt) {
        const __half* p = p0 + (size_t)mt * 16 * rs;
        a[mt * 4 + 0] = __ldcg((const uint32_t*)(p));
        a[mt * 4 + 1] = __ldcg((const uint32_t*)(p + 8 * rs));
        a[mt * 4 + 2] = __ldcg((const uint32_t*)(p + 8));
        a[mt * 4 + 3] = __ldcg((const uint32_t*)(p + 8 * rs + 8));
    }
}

__device__ __forceinline__ void mma16(float acc[4][4][4], const uint32_t a[16],
                                      const uint32_t Bj[4][2]) {
    #pragma unroll
    for (int mt = 0; mt < 4; ++mt)
        #pragma unroll
        for (int nt = 0; nt < 4; ++nt)
            mma_f16(acc[mt][nt], a[mt*4+0], a[mt*4+1], a[mt*4+2], a[mt*4+3],
                    Bj[nt][0], Bj[nt][1]);
}

__global__ void __launch_bounds__(NTH, 1)
lstm_kernel(const float* __restrict__ W_ih,
            const float* __restrict__ W_hh,
            const float* __restrict__ b_ih,
            const float* __restrict__ b_hh)
{
    extern __shared__ float4 RB[];   // [8 warps][16 tiles][32 lanes] partial C frags (64KB)

    const int tid  = threadIdx.x;
    const int bid  = blockIdx.x;
    const int w    = tid >> 5;
    const int lane = tid & 31;
    const int gid  = lane >> 2;
    const int tig  = lane & 3;

    // ---- one-time: gather B fragments (fp16) into registers ---------------
    // k16 chunks: h-chunks 0..31 (warp w owns w*4+j, j=0..3),
    //             x-chunks 32..47 (warp w owns 32 + w*2 + j, j=0..1)
    uint32_t Bv[6][4][2];
    #pragma unroll
    for (int j = 0; j < 6; ++j) {
        const int C  = (j < 4) ? (w * 4 + j) : (32 + w * 2 + (j - 4));
        const int k0 = C * 16 + 2 * tig;
        #pragma unroll
        for (int nt = 0; nt < 4; ++nt) {
            int nl   = nt * 8 + gid;
            int grow = (nl & 3) * HDIM + bid * NH + (nl >> 2);
            float v0, v1, v2, v3;
            if (C < 32) {
                const float* p = W_hh + (size_t)grow * HDIM + k0;
                v0 = p[0]; v1 = p[1]; v2 = p[8]; v3 = p[9];
            } else {
                const float* p = W_ih + (size_t)grow * IDIM + (k0 - HDIM);
                v0 = p[0]; v1 = p[1]; v2 = p[8]; v3 = p[9];
            }
            Bv[j][nt][0] = h2u(__floats2half2_rn(v0, v1));
            Bv[j][nt][1] = h2u(__floats2half2_rn(v2, v3));
        }
    }

    // ---- cell ownership: this thread finalizes 2 LSTM cells ---------------
    const int jj  = (w & 3) * 2 + (tig >> 1);
    const int col = bid * NH + jj;
    const float bI = b_ih[0*HDIM + col] + b_hh[0*HDIM + col];
    const float bF = b_ih[1*HDIM + col] + b_hh[1*HDIM + col];
    const float bG = b_ih[2*HDIM + col] + b_hh[2*HDIM + col];
    const float bO = b_ih[3*HDIM + col] + b_hh[3*HDIM + col];
    float creg[2] = {0.f, 0.f};

    // invariant x base: row gid, col = (w*2)*16 + 2*tig of the x-chunk region
    const __half* xp0 = &g_x[0][0][0] + (size_t)gid * TSTEPS * IDIM
                        + (w * 2) * 16 + 2 * tig;

    for (int t = 0; t < TSTEPS; ++t) {
        float acc[4][4][4];
        #pragma unroll
        for (int mt = 0; mt < 4; ++mt)
            #pragma unroll
            for (int nt = 0; nt < 4; ++nt)
                #pragma unroll
                for (int e = 0; e < 4; ++e) acc[mt][nt][e] = 0.f;

        // ---------- x phase (independent of the barrier) ----------
        {
            const __half* xb = xp0 + (size_t)t * IDIM;
            uint32_t A0[16], A1[16];
            loadA(A0, xb, TSTEPS * IDIM);
            loadA(A1, xb + 16, TSTEPS * IDIM);
            mma16(acc, A0, Bv[4]);
            mma16(acc, A1, Bv[5]);
        }

        // ---------- wait for h_t ----------
        if (t > 0) {
            if (tid == 0) {
                volatile unsigned int* p = &g_bar[t - 1];
                while (*p < (unsigned)GB) { }
            }
            __syncthreads();
        }

        // ---------- h phase (4 chunks, double-buffered) ----------
        {
            const __half* hb = &g_h[t & 1][0][0] + (size_t)gid * HDIM
                               + (w * 4) * 16 + 2 * tig;
            uint32_t A0[16], A1[16];
            loadA(A0, hb, HDIM);
            #pragma unroll
            for (int j = 0; j < 4; ++j) {
                if (j < 3) loadA((j & 1) ? A0 : A1, hb + (j + 1) * 16, HDIM);
                mma16(acc, (j & 1) ? A1 : A0, Bv[j]);
            }
        }

        // ---------- cross-warp k-reduction in fragment space ----------
        #pragma unroll
        for (int mt = 0; mt < 4; ++mt)
            #pragma unroll
            for (int nt = 0; nt < 4; ++nt)
                RB[(w * 16 + mt * 4 + nt) * 32 + lane] =
                    make_float4(acc[mt][nt][0], acc[mt][nt][1], acc[mt][nt][2], acc[mt][nt][3]);
        __syncthreads();

        __half* __restrict__ hnext = &g_h[(t + 1) & 1][0][0];
        const bool odd = (tig & 1);

        #pragma unroll
        for (int pos = 0; pos < 2; ++pos) {
            const int s = w + pos * 8;
            float4 F = RB[(0 * 16 + s) * 32 + lane];
            #pragma unroll
            for (int ws = 1; ws < 8; ++ws) {
                float4 T = RB[(ws * 16 + s) * 32 + lane];
                F.x += T.x; F.y += T.y; F.z += T.z; F.w += T.w;
            }
            // exchange gate pairs: even lane ends with cell b_lo, odd with b_hi
            float sx = odd ? F.x : F.z;
            float sy = odd ? F.y : F.w;
            float rx = __shfl_xor_sync(0xffffffffu, sx, 1);
            float ry = __shfl_xor_sync(0xffffffffu, sy, 1);
            float gi = odd ? rx : F.x;
            float gf = odd ? ry : F.y;
            float gg = odd ? F.z : rx;
            float go = odd ? F.w : ry;

            gi = sigf(gi + bI);
            gf = sigf(gf + bF);
            go = sigf(go + bO);
            gg = tanhff(gg + bG);
            float c = gf * creg[pos] + gi * gg;
            creg[pos] = c;
            float hv = go * tanhff(c);

            const int mt = s >> 2;
            const int b  = mt * 16 + gid + (odd ? 8 : 0);
            hnext[b * HDIM + col] = __float2half(hv);
        }

        // ---------- release h_{t+1} ----------
        __threadfence();
        __syncthreads();
        if (tid == 0) atomicAdd(&g_bar[t], 1u);
    }
}

__global__ void fc_kernel(const float* __restrict__ W_fc,
                          const float* __restrict__ b_fc,
                          float* __restrict__ out)
{
    int b    = blockIdx.x;
    int warp = threadIdx.x >> 5;
    int lane = threadIdx.x & 31;
    if (warp >= ODIM) return;
    const __half* h = &g_h[0][b][0];   // T even -> final h in buffer 0
    float acc = 0.f;
    for (int k = lane; k < HDIM; k += 32)
        acc += __half2float(h[k]) * W_fc[warp * HDIM + k];
    #pragma unroll
    for (int off = 16; off; off >>= 1)
        acc += __shfl_xor_sync(0xffffffffu, acc, off);
    if (lane == 0) out[b * ODIM + warp] = acc + b_fc[warp];
}

extern "C" void kernel_launch(void* const* d_in, const int* in_sizes, int n_in,
                              void* d_out, int out_size)
{
    const float* x    = (const float*)d_in[0];
    const float* W_ih = (const float*)d_in[1];
    const float* W_hh = (const float*)d_in[2];
    const float* b_ih = (const float*)d_in[3];
    const float* b_hh = (const float*)d_in[4];
    const float* W_fc = (const float*)d_in[5];
    const float* b_fc = (const float*)d_in[6];
    float* out = (float*)d_out;

    const int SMEM = 8 * 16 * 32 * (int)sizeof(float4);   // 64 KB
    cudaFuncSetAttribute(lstm_kernel,
                         cudaFuncAttributeMaxDynamicSharedMemorySize, SMEM);

    init_kernel<<<64, 256>>>();
    convert_x_kernel<<<2048, 256>>>(x);
    lstm_kernel<<<GB, NTH, SMEM>>>(W_ih, W_hh, b_ih, b_hh);
    fc_kernel<<<BATCH, 320>>>(W_fc, b_fc, out);
}

// round 10
// speedup vs baseline: 1.7439x; 1.0017x over previous
#include <cuda_runtime.h>
#include <cuda_fp16.h>
#include <cstdint>

#define IDIM    256
#define HDIM    512
#define ODIM    10
#define BATCH   64
#define TSTEPS  2048
#define GB      64          // grid blocks (all co-resident)
#define NTH     256         // 8 warps
#define NH      8           // h columns owned per block

// persistent device state (static __device__ is the sanctioned scratch path)
__device__ __half       g_h[2][BATCH][HDIM];          // double-buffered hidden state (fp16)
__device__ __half       g_x[BATCH][TSTEPS][IDIM];     // fp16 copy of x (converted once)
__device__ unsigned int g_bar[TSTEPS];                // per-step arrival counters

__device__ __forceinline__ uint32_t h2u(__half2 v) {
    uint32_t r;
    __builtin_memcpy(&r, &v, sizeof(r));
    return r;
}

__device__ __forceinline__ void mma_f16(float c[4],
                                        uint32_t a0, uint32_t a1, uint32_t a2, uint32_t a3,
                                        uint32_t b0, uint32_t b1) {
    asm("mma.sync.aligned.m16n8k16.row.col.f32.f16.f16.f32 "
        "{%0,%1,%2,%3}, {%4,%5,%6,%7}, {%8,%9}, {%0,%1,%2,%3};"
        : "+f"(c[0]), "+f"(c[1]), "+f"(c[2]), "+f"(c[3])
        : "r"(a0), "r"(a1), "r"(a2), "r"(a3), "r"(b0), "r"(b1));
}

__device__ __forceinline__ float sigf(float x)  { return 1.f / (1.f + __expf(-x)); }
__device__ __forceinline__ float tanhff(float x){ return 1.f - 2.f / (__expf(2.f * x) + 1.f); }

__global__ void init_kernel() {
    int idx = blockIdx.x * blockDim.x + threadIdx.x;
    int stride = gridDim.x * blockDim.x;
    __half* h = &g_h[0][0][0];
    for (int i = idx; i < 2 * BATCH * HDIM; i += stride) h[i] = __float2half(0.f);
    for (int i = idx; i < TSTEPS; i += stride) g_bar[i] = 0u;
}

// one-time fp32 -> fp16 conversion of x (8 floats / thread-iter)
__global__ void convert_x_kernel(const float* __restrict__ x) {
    const int N8 = BATCH * TSTEPS * IDIM / 8;
    uint2* dst = (uint2*)&g_x[0][0][0];
    int idx = blockIdx.x * blockDim.x + threadIdx.x;
    int stride = gridDim.x * blockDim.x;
    for (int i = idx; i < N8; i += stride) {
        float4 v0 = __ldcg((const float4*)x + 2 * i);
        float4 v1 = __ldcg((const float4*)x + 2 * i + 1);
        uint2 o;
        o.x = h2u(__floats2half2_rn(v0.x, v0.y));
        o.y = h2u(__floats2half2_rn(v0.z, v0.w));
        dst[2 * i] = o;
        o.x = h2u(__floats2half2_rn(v1.x, v1.y));
        o.y = h2u(__floats2half2_rn(v1.z, v1.w));
        dst[2 * i + 1] = o;
    }
}

// 16 half2 LDGs: A fragments for one k16 chunk over the 4 m16 tiles (64 rows).
// p0 points at (row 0, this chunk's col base + 2*tig), rs = row stride in halves.
__device__ __forceinline__ void loadA(uint32_t a[16], const __half* __restrict__ p0,
                                      int rs) {
    #pragma unroll
    for (int mt = 0; mt < 4; ++mt) {
        const __half* p = p0 + (size_t)mt * 16 * rs;
        a[mt * 4 + 0] = __ldcg((const uint32_t*)(p));
        a[mt * 4 + 1] = __ldcg((const uint32_t*)(p + 8 * rs));
        a[mt * 4 + 2] = __ldcg((const uint32_t*)(p + 8));
        a[mt * 4 + 3] = __ldcg((const uint32_t*)(p + 8 * rs + 8));
    }
}

__device__ __forceinline__ void mma16(float acc[4][4][4], const uint32_t a[16],
                                      const uint32_t Bj[4][2]) {
    #pragma unroll
    for (int mt = 0; mt < 4; ++mt)
        #pragma unroll
        for (int nt = 0; nt < 4; ++nt)
            mma_f16(acc[mt][nt], a[mt*4+0], a[mt*4+1], a[mt*4+2], a[mt*4+3],
                    Bj[nt][0], Bj[nt][1]);
}

__global__ void __launch_bounds__(NTH, 1)
lstm_kernel(const float* __restrict__ W_ih,
            const float* __restrict__ W_hh,
            const float* __restrict__ b_ih,
            const float* __restrict__ b_hh)
{
    extern __shared__ float4 RB[];   // [8 warps][16 tiles][32 lanes] partial C frags (64KB)

    const int tid  = threadIdx.x;
    const int bid  = blockIdx.x;
    const int w    = tid >> 5;
    const int lane = tid & 31;
    const int gid  = lane >> 2;
    const int tig  = lane & 3;

    // ---- one-time: gather B fragments (fp16) into registers ---------------
    // k16 chunks: h-chunks 0..31 (warp w owns w*4+j, j=0..3),
    //             x-chunks 32..47 (warp w owns 32 + w*2 + j, j=0..1)
    uint32_t Bv[6][4][2];
    #pragma unroll
    for (int j = 0; j < 6; ++j) {
        const int C  = (j < 4) ? (w * 4 + j) : (32 + w * 2 + (j - 4));
        const int k0 = C * 16 + 2 * tig;
        #pragma unroll
        for (int nt = 0; nt < 4; ++nt) {
            int nl   = nt * 8 + gid;
            int grow = (nl & 3) * HDIM + bid * NH + (nl >> 2);
            float v0, v1, v2, v3;
            if (C < 32) {
                const float* p = W_hh + (size_t)grow * HDIM + k0;
                v0 = p[0]; v1 = p[1]; v2 = p[8]; v3 = p[9];
            } else {
                const float* p = W_ih + (size_t)grow * IDIM + (k0 - HDIM);
                v0 = p[0]; v1 = p[1]; v2 = p[8]; v3 = p[9];
            }
            Bv[j][nt][0] = h2u(__floats2half2_rn(v0, v1));
            Bv[j][nt][1] = h2u(__floats2half2_rn(v2, v3));
        }
    }

    // ---- cell ownership: this thread finalizes 2 LSTM cells ---------------
    const int jj  = (w & 3) * 2 + (tig >> 1);
    const int col = bid * NH + jj;
    const float bI = b_ih[0*HDIM + col] + b_hh[0*HDIM + col];
    const float bF = b_ih[1*HDIM + col] + b_hh[1*HDIM + col];
    const float bG = b_ih[2*HDIM + col] + b_hh[2*HDIM + col];
    const float bO = b_ih[3*HDIM + col] + b_hh[3*HDIM + col];
    float creg[2] = {0.f, 0.f};

    // invariant x base: row gid, col = (w*2)*16 + 2*tig of the x-chunk region
    const __half* xp0 = &g_x[0][0][0] + (size_t)gid * TSTEPS * IDIM
                        + (w * 2) * 16 + 2 * tig;

    for (int t = 0; t < TSTEPS; ++t) {
        float acc[4][4][4];
        #pragma unroll
        for (int mt = 0; mt < 4; ++mt)
            #pragma unroll
            for (int nt = 0; nt < 4; ++nt)
                #pragma unroll
                for (int e = 0; e < 4; ++e) acc[mt][nt][e] = 0.f;

        // ---------- x phase (independent of the barrier) ----------
        {
            const __half* xb = xp0 + (size_t)t * IDIM;
            uint32_t A0[16], A1[16];
            loadA(A0, xb, TSTEPS * IDIM);
            loadA(A1, xb + 16, TSTEPS * IDIM);
            mma16(acc, A0, Bv[4]);
            mma16(acc, A1, Bv[5]);
        }

        // ---------- wait for h_t ----------
        if (t > 0) {
            if (tid == 0) {
                volatile unsigned int* p = &g_bar[t - 1];
                while (*p < (unsigned)GB) { }
            }
            __syncthreads();
        }

        // ---------- h phase (4 chunks, double-buffered) ----------
        {
            const __half* hb = &g_h[t & 1][0][0] + (size_t)gid * HDIM
                               + (w * 4) * 16 + 2 * tig;
            uint32_t A0[16], A1[16];
            loadA(A0, hb, HDIM);
            #pragma unroll
            for (int j = 0; j < 4; ++j) {
                if (j < 3) loadA((j & 1) ? A0 : A1, hb + (j + 1) * 16, HDIM);
                mma16(acc, (j & 1) ? A1 : A0, Bv[j]);
            }
        }

        // ---------- cross-warp k-reduction in fragment space ----------
        #pragma unroll
        for (int mt = 0; mt < 4; ++mt)
            #pragma unroll
            for (int nt = 0; nt < 4; ++nt)
                RB[(w * 16 + mt * 4 + nt) * 32 + lane] =
                    make_float4(acc[mt][nt][0], acc[mt][nt][1], acc[mt][nt][2], acc[mt][nt][3]);
        __syncthreads();

        __half* __restrict__ hnext = &g_h[(t + 1) & 1][0][0];
        const bool odd = (tig & 1);

        #pragma unroll
        for (int pos = 0; pos < 2; ++pos) {
            const int s = w + pos * 8;
            float4 F = RB[(0 * 16 + s) * 32 + lane];
            #pragma unroll
            for (int ws = 1; ws < 8; ++ws) {
                float4 T = RB[(ws * 16 + s) * 32 + lane];
                F.x += T.x; F.y += T.y; F.z += T.z; F.w += T.w;
            }
            // exchange gate pairs: even lane ends with cell b_lo, odd with b_hi
            float sx = odd ? F.x : F.z;
            float sy = odd ? F.y : F.w;
            float rx = __shfl_xor_sync(0xffffffffu, sx, 1);
            float ry = __shfl_xor_sync(0xffffffffu, sy, 1);
            float gi = odd ? rx : F.x;
            float gf = odd ? ry : F.y;
            float gg = odd ? F.z : rx;
            float go = odd ? F.w : ry;

            gi = sigf(gi + bI);
            gf = sigf(gf + bF);
            go = sigf(go + bO);
            gg = tanhff(gg + bG);
            float c = gf * creg[pos] + gi * gg;
            creg[pos] = c;
            float hv = go * tanhff(c);

            const int mt = s >> 2;
            const int b  = mt * 16 + gid + (odd ? 8 : 0);
            hnext[b * HDIM + col] = __float2half(hv);
        }

        // ---------- release h_{t+1} ----------
        __threadfence();
        __syncthreads();
        if (tid == 0) atomicAdd(&g_bar[t], 1u);
    }
}

__global__ void fc_kernel(const float* __restrict__ W_fc,
                          const float* __restrict__ b_fc,
                          float* __restrict__ out)
{
    int b    = blockIdx.x;
    int warp = threadIdx.x >> 5;
    int lane = threadIdx.x & 31;
    if (warp >= ODIM) return;
    const __half* h = &g_h[0][b][0];   // T even -> final h in buffer 0
    float acc = 0.f;
    for (int k = lane; k < HDIM; k += 32)
        acc += __half2float(h[k]) * W_fc[warp * HDIM + k];
    #pragma unroll
    for (int off = 16; off; off >>= 1)
        acc += __shfl_xor_sync(0xffffffffu, acc, off);
    if (lane == 0) out[b * ODIM + warp] = acc + b_fc[warp];
}

extern "C" void kernel_launch(void* const* d_in, const int* in_sizes, int n_in,
                              void* d_out, int out_size)
{
    const float* x    = (const float*)d_in[0];
    const float* W_ih = (const float*)d_in[1];
    const float* W_hh = (const float*)d_in[2];
    const float* b_ih = (const float*)d_in[3];
    const float* b_hh = (const float*)d_in[4];
    const float* W_fc = (const float*)d_in[5];
    const float* b_fc = (const float*)d_in[6];
    float* out = (float*)d_out;

    const int SMEM = 8 * 16 * 32 * (int)sizeof(float4);   // 64 KB
    cudaFuncSetAttribute(lstm_kernel,
                         cudaFuncAttributeMaxDynamicSharedMemorySize, SMEM);

    init_kernel<<<64, 256>>>();
    convert_x_kernel<<<2048, 256>>>(x);
    lstm_kernel<<<GB, NTH, SMEM>>>(W_ih, W_hh, b_ih, b_hh);
    fc_kernel<<<BATCH, 320>>>(W_fc, b_fc, out);
}

// round 14
// speedup vs baseline: 2.8314x; 1.6236x over previous
#include <cuda_runtime.h>
#include <cuda_fp16.h>
#include <cstdint>

#define IDIM    256
#define HDIM    512
#define ODIM    10
#define BATCH   64
#define TSTEPS  2048
#define GB      128         // grid blocks (all co-resident; <=148 SMs)
#define NTH     256         // 8 warps
#define NHC     8           // h columns owned per n-group

// persistent device state (static __device__ is the sanctioned scratch path)
__device__ __half       g_h[2][BATCH][HDIM];          // double-buffered hidden state (fp16)
__device__ __half       g_x[BATCH][TSTEPS][IDIM];     // fp16 copy of x (converted once)
__device__ unsigned int g_bar[TSTEPS];                // per-step arrival counters

__device__ __forceinline__ uint32_t h2u(__half2 v) {
    uint32_t r;
    __builtin_memcpy(&r, &v, sizeof(r));
    return r;
}

__device__ __forceinline__ void mma_f16(float c[4],
                                        uint32_t a0, uint32_t a1, uint32_t a2, uint32_t a3,
                                        uint32_t b0, uint32_t b1) {
    asm("mma.sync.aligned.m16n8k16.row.col.f32.f16.f16.f32 "
        "{%0,%1,%2,%3}, {%4,%5,%6,%7}, {%8,%9}, {%0,%1,%2,%3};"
        : "+f"(c[0]), "+f"(c[1]), "+f"(c[2]), "+f"(c[3])
        : "r"(a0), "r"(a1), "r"(a2), "r"(a3), "r"(b0), "r"(b1));
}

__device__ __forceinline__ float sigf(float x)  { return 1.f / (1.f + __expf(-x)); }
__device__ __forceinline__ float tanhff(float x){ return 1.f - 2.f / (__expf(2.f * x) + 1.f); }

__global__ void init_kernel() {
    int idx = blockIdx.x * blockDim.x + threadIdx.x;
    int stride = gridDim.x * blockDim.x;
    __half* h = &g_h[0][0][0];
    for (int i = idx; i < 2 * BATCH * HDIM; i += stride) h[i] = __float2half(0.f);
    for (int i = idx; i < TSTEPS; i += stride) g_bar[i] = 0u;
}

// one-time fp32 -> fp16 conversion of x (8 floats / thread-iter)
__global__ void convert_x_kernel(const float* __restrict__ x) {
    const int N8 = BATCH * TSTEPS * IDIM / 8;
    uint2* dst = (uint2*)&g_x[0][0][0];
    int idx = blockIdx.x * blockDim.x + threadIdx.x;
    int stride = gridDim.x * blockDim.x;
    for (int i = idx; i < N8; i += stride) {
        float4 v0 = __ldcg((const float4*)x + 2 * i);
        float4 v1 = __ldcg((const float4*)x + 2 * i + 1);
        uint2 o;
        o.x = h2u(__floats2half2_rn(v0.x, v0.y));
        o.y = h2u(__floats2half2_rn(v0.z, v0.w));
        dst[2 * i] = o;
        o.x = h2u(__floats2half2_rn(v1.x, v1.y));
        o.y = h2u(__floats2half2_rn(v1.z, v1.w));
        dst[2 * i + 1] = o;
    }
}

// 8 half2 LDGs: A fragments for one k16 chunk over the 2 m16 tiles (32 rows).
// p0 points at (row 0 of this block's m-slab, chunk col base + 2*tig).
__device__ __forceinline__ void loadA8(uint32_t a[8], const __half* __restrict__ p0,
                                       int rs) {
    #pragma unroll
    for (int mt = 0; mt < 2; ++mt) {
        const __half* p = p0 + (size_t)mt * 16 * rs;
        a[mt * 4 + 0] = __ldcg((const uint32_t*)(p));
        a[mt * 4 + 1] = __ldcg((const uint32_t*)(p + 8 * rs));
        a[mt * 4 + 2] = __ldcg((const uint32_t*)(p + 8));
        a[mt * 4 + 3] = __ldcg((const uint32_t*)(p + 8 * rs + 8));
    }
}

__device__ __forceinline__ void mma8(float acc[2][4][4], const uint32_t a[8],
                                     const uint32_t Bj[4][2]) {
    #pragma unroll
    for (int mt = 0; mt < 2; ++mt)
        #pragma unroll
        for (int nt = 0; nt < 4; ++nt)
            mma_f16(acc[mt][nt], a[mt*4+0], a[mt*4+1], a[mt*4+2], a[mt*4+3],
                    Bj[nt][0], Bj[nt][1]);
}

__global__ void __launch_bounds__(NTH, 1)
lstm_kernel(const float* __restrict__ W_ih,
            const float* __restrict__ W_hh,
            const float* __restrict__ b_ih,
            const float* __restrict__ b_hh)
{
    extern __shared__ float4 RB[];   // [8 warps][8 tiles][32 lanes] partial C frags (16KB)

    const int tid  = threadIdx.x;
    const int bid  = blockIdx.x;
    const int w    = tid >> 5;
    const int lane = tid & 31;
    const int gid  = lane >> 2;
    const int tig  = lane & 3;

    const int mg = bid & 1;          // m-group: batch rows mg*32 .. mg*32+31
    const int ng = bid >> 1;         // n-group: h cols ng*8 .. ng*8+7
    const int m0 = mg * 32;

    // ---- one-time: gather B fragments (fp16) into registers ---------------
    // k16 chunks: h-chunks 0..31 (warp w owns w*4+j, j=0..3),
    //             x-chunks 32..47 (warp w owns 32 + w*2 + j, j=0..1)
    uint32_t Bv[6][4][2];
    #pragma unroll
    for (int j = 0; j < 6; ++j) {
        const int C  = (j < 4) ? (w * 4 + j) : (32 + w * 2 + (j - 4));
        const int k0 = C * 16 + 2 * tig;
        #pragma unroll
        for (int nt = 0; nt < 4; ++nt) {
            int nl   = nt * 8 + gid;
            int grow = (nl & 3) * HDIM + ng * NHC + (nl >> 2);
            float v0, v1, v2, v3;
            if (C < 32) {
                const float* p = W_hh + (size_t)grow * HDIM + k0;
                v0 = p[0]; v1 = p[1]; v2 = p[8]; v3 = p[9];
            } else {
                const float* p = W_ih + (size_t)grow * IDIM + (k0 - HDIM);
                v0 = p[0]; v1 = p[1]; v2 = p[8]; v3 = p[9];
            }
            Bv[j][nt][0] = h2u(__floats2half2_rn(v0, v1));
            Bv[j][nt][1] = h2u(__floats2half2_rn(v2, v3));
        }
    }

    // ---- cell ownership: this thread finalizes 1 LSTM cell ----------------
    // reduction slot s = w: mt = w>>2, nt = w&3
    const int jj  = (w & 3) * 2 + (tig >> 1);
    const int col = ng * NHC + jj;
    const float bI = b_ih[0*HDIM + col] + b_hh[0*HDIM + col];
    const float bF = b_ih[1*HDIM + col] + b_hh[1*HDIM + col];
    const float bG = b_ih[2*HDIM + col] + b_hh[2*HDIM + col];
    const float bO = b_ih[3*HDIM + col] + b_hh[3*HDIM + col];
    float creg = 0.f;

    // invariant x base: row m0+gid, col = w*32 + 2*tig
    const __half* xp0 = &g_x[0][0][0] + (size_t)(m0 + gid) * TSTEPS * IDIM
                        + w * 32 + 2 * tig;

    // preload x A-fragments for t=0
    uint32_t xA0[8], xA1[8];
    loadA8(xA0, xp0,      TSTEPS * IDIM);
    loadA8(xA1, xp0 + 16, TSTEPS * IDIM);

    for (int t = 0; t < TSTEPS; ++t) {
        float acc[2][4][4];
        #pragma unroll
        for (int mt = 0; mt < 2; ++mt)
            #pragma unroll
            for (int nt = 0; nt < 4; ++nt)
                #pragma unroll
                for (int e = 0; e < 4; ++e) acc[mt][nt][e] = 0.f;

        // ---------- x phase: pure register mma, overlaps barrier wait ------
        mma8(acc, xA0, Bv[4]);
        mma8(acc, xA1, Bv[5]);

        // ---------- wait for h_t ----------
        if (t > 0) {
            if (tid == 0) {
                volatile unsigned int* p = &g_bar[t - 1];
                while (*p < (unsigned)GB) { }
            }
            __syncthreads();
        }

        // ---------- h phase (4 chunks, double-buffered) ----------
        {
            const __half* hb = &g_h[t & 1][0][0] + (size_t)(m0 + gid) * HDIM
                               + w * 64 + 2 * tig;
            uint32_t A0[8], A1[8];
            loadA8(A0, hb, HDIM);
            #pragma unroll
            for (int j = 0; j < 4; ++j) {
                if (j < 3) loadA8((j & 1) ? A0 : A1, hb + (j + 1) * 16, HDIM);
                mma8(acc, (j & 1) ? A1 : A0, Bv[j]);
            }
        }

        // ---------- prefetch x for t+1 (latency hidden behind epilogue) ----
        if (t + 1 < TSTEPS) {
            const __half* xb = xp0 + (size_t)(t + 1) * IDIM;
            loadA8(xA0, xb,      TSTEPS * IDIM);
            loadA8(xA1, xb + 16, TSTEPS * IDIM);
        }

        // ---------- cross-warp k-reduction in fragment space ----------
        #pragma unroll
        for (int mt = 0; mt < 2; ++mt)
            #pragma unroll
            for (int nt = 0; nt < 4; ++nt)
                RB[(w * 8 + mt * 4 + nt) * 32 + lane] =
                    make_float4(acc[mt][nt][0], acc[mt][nt][1], acc[mt][nt][2], acc[mt][nt][3]);
        __syncthreads();

        __half* __restrict__ hnext = &g_h[(t + 1) & 1][0][0];
        const bool odd = (tig & 1);

        {
            // warp w reduces slot s = w across the 8 warps
            float4 F = RB[(0 * 8 + w) * 32 + lane];
            #pragma unroll
            for (int ws = 1; ws < 8; ++ws) {
                float4 T = RB[(ws * 8 + w) * 32 + lane];
                F.x += T.x; F.y += T.y; F.z += T.z; F.w += T.w;
            }
            // exchange gate pairs: even lane ends with cell row gid, odd with gid+8
            float sx = odd ? F.x : F.z;
            float sy = odd ? F.y : F.w;
            float rx = __shfl_xor_sync(0xffffffffu, sx, 1);
            float ry = __shfl_xor_sync(0xffffffffu, sy, 1);
            float gi = odd ? rx : F.x;
            float gf = odd ? ry : F.y;
            float gg = odd ? F.z : rx;
            float go = odd ? F.w : ry;

            gi = sigf(gi + bI);
            gf = sigf(gf + bF);
            go = sigf(go + bO);
            gg = tanhff(gg + bG);
            float c = gf * creg + gi * gg;
            creg = c;
            float hv = go * tanhff(c);

            const int mt = w >> 2;
            const int b  = m0 + mt * 16 + gid + (odd ? 8 : 0);
            hnext[b * HDIM + col] = __float2half(hv);
        }

        // ---------- release h_{t+1} ----------
        __threadfence();
        __syncthreads();
        if (tid == 0) atomicAdd(&g_bar[t], 1u);
    }
}

__global__ void fc_kernel(const float* __restrict__ W_fc,
                          const float* __restrict__ b_fc,
                          float* __restrict__ out)
{
    int b    = blockIdx.x;
    int warp = threadIdx.x >> 5;
    int lane = threadIdx.x & 31;
    if (warp >= ODIM) return;
    const __half* h = &g_h[0][b][0];   // T even -> final h in buffer 0
    float acc = 0.f;
    for (int k = lane; k < HDIM; k += 32)
        acc += __half2float(h[k]) * W_fc[warp * HDIM + k];
    #pragma unroll
    for (int off = 16; off; off >>= 1)
        acc += __shfl_xor_sync(0xffffffffu, acc, off);
    if (lane == 0) out[b * ODIM + warp] = acc + b_fc[warp];
}

extern "C" void kernel_launch(void* const* d_in, const int* in_sizes, int n_in,
                              void* d_out, int out_size)
{
    const float* x    = (const float*)d_in[0];
    const float* W_ih = (const float*)d_in[1];
    const float* W_hh = (const float*)d_in[2];
    const float* b_ih = (const float*)d_in[3];
    const float* b_hh = (const float*)d_in[4];
    const float* W_fc = (const float*)d_in[5];
    const float* b_fc = (const float*)d_in[6];
    float* out = (float*)d_out;

    const int SMEM = 8 * 8 * 32 * (int)sizeof(float4);   // 16 KB
    cudaFuncSetAttribute(lstm_kernel,
                         cudaFuncAttributeMaxDynamicSharedMemorySize, SMEM);

    init_kernel<<<64, 256>>>();
    convert_x_kernel<<<2048, 256>>>(x);
    lstm_kernel<<<GB, NTH, SMEM>>>(W_ih, W_hh, b_ih, b_hh);
    fc_kernel<<<BATCH, 320>>>(W_fc, b_fc, out);
}